// round 14
// baseline (speedup 1.0000x reference)
#include <cuda_runtime.h>
#include <math.h>
#include <stdint.h>

typedef unsigned long long u64;

#define CAP 65536

// ---- device scratch (no allocations allowed) ----
__device__ float    g_imgup[2896*2896];
__device__ float    g_img2 [1448*1448];
__device__ float    g_img3 [1024*1023];
__device__ float    g_img4 [724*723];
__device__ float    g_img5 [512*511];
__device__ float    g_blurB[2048*2048];
__device__ float4   g_rtab [6601];
__device__ u64      g_cand[6*CAP];
__device__ u64      g_pool[12288];
__device__ int      g_cnt[8];   // [0..5]=per-level cand count, [6]=pool

__constant__ int   c_W[6]    = {2896,2048,1448,1023,723,511};
__constant__ int   c_S[6]    = {2896,2048,1448,1024,724,512};
__constant__ float c_fact[6] = {(float)(2048.0/2896.0), 1.0f, (float)(2048.0/1448.0),
                                (float)(2048.0/1023.0), (float)(2048.0/723.0), (float)(2048.0/511.0)};
__constant__ float c_scal[6] = {(float)(2048.0/2896.0*22.0), 22.0f, (float)(2048.0/1448.0*22.0),
                                (float)(2048.0/1023.0*22.0), (float)(2048.0/723.0*22.0), (float)(2048.0/511.0*22.0)};
__constant__ int   c_k[6]    = {1040,1560,1820,1950,2015,2047};

// fused-kernel tiling: strips 224 wide x 128 tall
__constant__ int c_cumF[6] = {0, 299, 459, 543, 583, 607};   // total 619
__constant__ int c_fbx[6] = {13, 10, 7, 5, 4, 3};

// resize-weight-table layout
__constant__ int   c_toff[5] = {0, 2896, 4344, 5367, 6090};  // total 6601
__constant__ int   c_rsw[5]  = {2048, 2048, 1448, 1023, 723};
__constant__ float c_rinv[5] = {(float)(2048.0/2896.0), (float)(2048.0/1448.0),
                                (float)(1448.0/1023.0), (float)(1023.0/723.0),
                                (float)(723.0/511.0)};

union HistBuf { int hist[4096]; u64 buf[2048]; };

__device__ __forceinline__ float4 f4max(float4 a, float4 b)
{
    return make_float4(fmaxf(a.x,b.x), fmaxf(a.y,b.y), fmaxf(a.z,b.z), fmaxf(a.w,b.w));
}

// ---------------------------------------------------------------------------
// init: zero counters + build resize weight tables (bit-identical arithmetic
// to the per-pixel resize math of the R5 passing kernel).
__global__ void __launch_bounds__(256) k_init()
{
    int idx = blockIdx.x * 256 + threadIdx.x;
    if (idx < 8) g_cnt[idx] = 0;
    if (idx >= 6601) return;
    int r = 4;
    while (idx < c_toff[r]) --r;
    int d  = idx - c_toff[r];
    int sw = c_rsw[r];
    float invs = c_rinv[r];

    float sx = __fadd_rn(__fmul_rn(__fadd_rn((float)d, 0.5f), invs), -0.5f);
    int j0 = (int)floorf(sx), j1 = j0 + 1;
    float w0 = __fadd_rn(1.0f, -__fadd_rn(sx, -(float)j0));
    float w1 = __fadd_rn(1.0f, -__fadd_rn((float)j1, -sx));
    bool v0 = (j0 >= 0), v1 = (j1 <= sw - 1);
    int C0 = v0 ? j0 : 0, C1 = v1 ? j1 : sw - 1;
    float n0, n1;
    if (v0 && v1) {
        float tot = __fadd_rn(w0, w1);
        n0 = __fdiv_rn(w0, tot); n1 = __fdiv_rn(w1, tot);
    } else if (v0) { n0 = 1.0f; n1 = 0.0f; }
    else           { n0 = 0.0f; n1 = 1.0f; }
    g_rtab[idx] = make_float4(n0, n1, __int_as_float(C0), __int_as_float(C1));
}

// ---------------------------------------------------------------------------
// Table-driven bilinear resize (jax half-pixel semantics baked into tables).
__global__ void __launch_bounds__(256) k_resize2(const float* __restrict__ in, int sIn,
                         float* __restrict__ dst, int sOut, int dw, int tab)
{
    int dy  = blockIdx.y;
    int dx0 = (blockIdx.x * 256 + threadIdx.x) * 4;
    if (dx0 >= dw) return;

    float4 ye = g_rtab[tab + dy];
    float n0y = ye.x, n1y = ye.y;
    const float* r0 = in + (size_t)__float_as_int(ye.z) * sIn;
    const float* r1 = in + (size_t)__float_as_int(ye.w) * sIn;

    float res[4];
    int nn = dw - dx0; if (nn > 4) nn = 4;
    #pragma unroll
    for (int c = 0; c < 4; ++c) {
        if (c >= nn) break;
        float4 xe = g_rtab[tab + dx0 + c];
        float n0x = xe.x, n1x = xe.y;
        int cx0 = __float_as_int(xe.z), cx1 = __float_as_int(xe.w);
        float p00 = __ldg(r0 + cx0), p01 = __ldg(r0 + cx1);
        float p10 = __ldg(r1 + cx0), p11 = __ldg(r1 + cx1);
        float c0 = __fadd_rn(__fmul_rn(n0y, p00), __fmul_rn(n1y, p10));
        float c1 = __fadd_rn(__fmul_rn(n0y, p01), __fmul_rn(n1y, p11));
        res[c] = __fadd_rn(__fmul_rn(n0x, c0), __fmul_rn(n1x, c1));
    }
    float* orow = dst + (size_t)dy * sOut;
    if (nn == 4) *(float4*)(orow + dx0) = make_float4(res[0], res[1], res[2], res[3]);
    else for (int c = 0; c < nn; ++c) orow[dx0 + c] = res[c];
}

// ---------------------------------------------------------------------------
__device__ __forceinline__ int reflect_i(int i, int n)
{
    if (i < 0) return -i;
    if (i >= n) return 2 * n - 2 - i;
    return i;
}

// Fused separable 5-tap gaussian blur (reflect): V in registers, H via smem.
__global__ void __launch_bounds__(128) k_blurVH(const float* __restrict__ in,
        float* __restrict__ out, int S, int W, int H,
        float g0, float g1, float g2)
{
    __shared__ __align__(16) float sv[8][512];
    int t  = threadIdx.x;
    int xb = blockIdx.x * 504;
    int yb = blockIdx.y * 8;
    int xg = xb - 4 + t * 4;

    float4 raw[12];
    bool fast = (xg >= 0) && (xg + 4 <= W);
    #pragma unroll
    for (int r = 0; r < 12; ++r) {
        const float* rowp = in + (size_t)reflect_i(yb - 2 + r, H) * S;
        if (fast) {
            raw[r] = __ldg((const float4*)(rowp + xg));
        } else {
            float t0 = __ldg(rowp + reflect_i(xg,     W));
            float t1 = __ldg(rowp + reflect_i(xg + 1, W));
            float t2 = __ldg(rowp + reflect_i(xg + 2, W));
            float t3 = __ldg(rowp + reflect_i(xg + 3, W));
            raw[r] = make_float4(t0, t1, t2, t3);
        }
    }
    #pragma unroll
    for (int r = 0; r < 8; ++r) {
        float4 a = raw[r], b = raw[r+1], c = raw[r+2], d = raw[r+3], e = raw[r+4];
        float4 vb;
        vb.x = fmaf(g0, e.x, fmaf(g1, d.x, fmaf(g2, c.x, fmaf(g1, b.x, g0 * a.x))));
        vb.y = fmaf(g0, e.y, fmaf(g1, d.y, fmaf(g2, c.y, fmaf(g1, b.y, g0 * a.y))));
        vb.z = fmaf(g0, e.z, fmaf(g1, d.z, fmaf(g2, c.z, fmaf(g1, b.z, g0 * a.z))));
        vb.w = fmaf(g0, e.w, fmaf(g1, d.w, fmaf(g2, c.w, fmaf(g1, b.w, g0 * a.w))));
        *(float4*)&sv[r][t * 4] = vb;
    }
    __syncthreads();
    if (t >= 126) return;
    int xo = xb + t * 4;
    if (xo >= W) return;
    #pragma unroll
    for (int r = 0; r < 8; ++r) {
        int yo = yb + r;
        if (yo >= H) break;
        float v[12];
        #pragma unroll
        for (int q = 0; q < 3; ++q) {
            float4 a = *(float4*)&sv[r][t * 4 + q * 4];
            v[q*4] = a.x; v[q*4+1] = a.y; v[q*4+2] = a.z; v[q*4+3] = a.w;
        }
        float res[4];
        #pragma unroll
        for (int c = 0; c < 4; ++c) {
            res[c] = fmaf(g0, v[c + 6], fmaf(g1, v[c + 5],
                     fmaf(g2, v[c + 4], fmaf(g1, v[c + 3], g0 * v[c + 2]))));
        }
        float* orow = out + (size_t)yo * S;
        if (xo + 4 <= W) {
            *(float4*)(orow + xo) = make_float4(res[0], res[1], res[2], res[3]);
        } else {
            for (int c = 0; c < 4; ++c) if (xo + c < W) orow[xo + c] = res[c];
        }
    }
}

// ---------------------------------------------------------------------------
// FUSED detection: per 224w x 128h segment, stream rows downward keeping a raw
// ring (8 rows) and a rowmax ring (16 rows) in smem; emit candidates directly.
// Conv FMA chain is bit-identical to all passing kernels (ky asc, kx asc).
// At a semi-candidate, score == rowmax center, so candidates are recovered
// exactly from the ring without any global score/rmax storage.
__global__ void __launch_bounds__(128) k_fused(const float* __restrict__ imgOrig,
        const float* __restrict__ wp, const float* __restrict__ bp)
{
    __shared__ float swt[25];
    __shared__ float sbv;
    __shared__ __align__(16) float raw[8][248];
    __shared__ __align__(16) float sc[2][240];
    __shared__ __align__(16) float ring[16][224];
    __shared__ unsigned char semi[16][56];

    int t = threadIdx.x;
    if (t < 25) swt[t] = __ldg(wp + t);
    if (t == 31) sbv = __ldg(bp);

    int bid = blockIdx.x;
    int l = 5;
    while (bid < c_cumF[l]) --l;
    int rem  = bid - c_cumF[l];
    int bx   = c_fbx[l];
    int yblk = rem / bx;
    int xblk = rem - yblk * bx;
    int W = c_W[l], H = W, S = c_S[l];
    const float* img;
    switch (l) {
        case 0: img = g_imgup; break;
        case 1: img = imgOrig; break;
        case 2: img = g_img2;  break;
        case 3: img = g_img3;  break;
        case 4: img = g_img4;  break;
        default: img = g_img5; break;
    }
    int y0   = yblk * 128;
    int yend = y0 + 128; if (yend > H) yend = H;
    int xb   = xblk * 224;

    int zstart = y0 - 7; if (zstart < 0) zstart = 0;
    int zend   = yend - 1 + 7; if (zend > H - 1) zend = H - 1;

    int h = t >> 6;      // row half: 0 or 1
    int q = t & 63;

    bool xfast = (xb >= 12) && (xb + 236 <= W);

    // prime raw rows zstart-2 .. zstart+3 (clamped content, slot = row & 7)
    #pragma unroll
    for (int rr = 0; rr < 6; rr += 2) {
        int zz = zstart - 2 + rr + h;
        int yy = zz < 0 ? 0 : (zz > H - 1 ? H - 1 : zz);
        const float* rp = img + (size_t)yy * S;
        int slot = zz & 7;
        if (xfast) {
            if (q < 62)
                *(float4*)&raw[slot][q * 4] = __ldg((const float4*)(rp + xb - 12 + q * 4));
        } else {
            for (int i = q; i < 248; i += 64) {
                int x = xb - 12 + i;
                x = x < 0 ? 0 : (x > W - 1 ? W - 1 : x);
                raw[slot][i] = __ldg(rp + x);
            }
        }
    }
    __syncthreads();

    float wreg[25];
    #pragma unroll
    for (int i = 0; i < 25; ++i) wreg[i] = swt[i];
    float breg = sbv;

    int nextE = y0;

    for (int z = zstart; z <= zend; z += 2) {
        int lastz = (z + 1 <= zend) ? z + 1 : zend;
        int myz = z + h;
        bool zvalid = (myz <= zend);

        // ---- conv row myz -> sc[h] (cols xb-7 .. xb+230, sc idx j) ----
        if (zvalid && q < 60) {
            int j0 = q * 4;
            bool rowok = (myz >= 15 && myz < H - 15);
            float a0 = breg, a1 = breg, a2 = breg, a3 = breg;
            #pragma unroll
            for (int ky = 0; ky < 5; ++ky) {
                int slot = (myz - 2 + ky) & 7;
                float4 A = *(const float4*)&raw[slot][j0];
                float4 B = *(const float4*)&raw[slot][j0 + 4];
                float4 C = *(const float4*)&raw[slot][j0 + 8];
                float v[12] = {A.x,A.y,A.z,A.w, B.x,B.y,B.z,B.w, C.x,C.y,C.z,C.w};
                const float* wr = &wreg[ky * 5];
                a0 = fmaf(wr[0], v[3], a0); a0 = fmaf(wr[1], v[4], a0);
                a0 = fmaf(wr[2], v[5], a0); a0 = fmaf(wr[3], v[6], a0);
                a0 = fmaf(wr[4], v[7], a0);
                a1 = fmaf(wr[0], v[4], a1); a1 = fmaf(wr[1], v[5], a1);
                a1 = fmaf(wr[2], v[6], a1); a1 = fmaf(wr[3], v[7], a1);
                a1 = fmaf(wr[4], v[8], a1);
                a2 = fmaf(wr[0], v[5], a2); a2 = fmaf(wr[1], v[6], a2);
                a2 = fmaf(wr[2], v[7], a2); a2 = fmaf(wr[3], v[8], a2);
                a2 = fmaf(wr[4], v[9], a2);
                a3 = fmaf(wr[0], v[6], a3); a3 = fmaf(wr[1], v[7], a3);
                a3 = fmaf(wr[2], v[8], a3); a3 = fmaf(wr[3], v[9], a3);
                a3 = fmaf(wr[4], v[10], a3);
            }
            int xg = xb - 7 + j0;
            float4 o;
            o.x = (rowok && xg + 0 >= 15 && xg + 0 < W - 15) ? a0 : 0.f;
            o.y = (rowok && xg + 1 >= 15 && xg + 1 < W - 15) ? a1 : 0.f;
            o.z = (rowok && xg + 2 >= 15 && xg + 2 < W - 15) ? a2 : 0.f;
            o.w = (rowok && xg + 3 >= 15 && xg + 3 < W - 15) ? a3 : 0.f;
            *(float4*)&sc[h][j0] = o;
        }
        __syncthreads();

        // ---- rowmax row myz -> ring + semi nibbles ----
        if (zvalid && q < 56) {
            int u0 = q * 4;
            float4 q0 = *(const float4*)&sc[h][u0];
            float4 q1 = *(const float4*)&sc[h][u0 + 4];
            float4 q2 = *(const float4*)&sc[h][u0 + 8];
            float4 q3 = *(const float4*)&sc[h][u0 + 12];
            float4 q4 = *(const float4*)&sc[h][u0 + 16];
            float f[20] = {q0.x,q0.y,q0.z,q0.w, q1.x,q1.y,q1.z,q1.w,
                           q2.x,q2.y,q2.z,q2.w, q3.x,q3.y,q3.z,q3.w,
                           q4.x,q4.y,q4.z,q4.w};
            float core = f[4];
            #pragma unroll
            for (int i = 5; i <= 14; ++i) core = fmaxf(core, f[i]);
            float m0 = fmaxf(fmaxf(fmaxf(fmaxf(core, f[0]), f[1]), f[2]), f[3]);
            float m1 = fmaxf(fmaxf(fmaxf(fmaxf(core, f[1]), f[2]), f[3]), f[15]);
            float m2 = fmaxf(fmaxf(fmaxf(fmaxf(core, f[2]), f[3]), f[15]), f[16]);
            float m3 = fmaxf(fmaxf(fmaxf(fmaxf(core, f[3]), f[15]), f[16]), f[17]);
            float s0 = f[7], s1 = f[8], s2 = f[9], s3 = f[10];
            unsigned nb = 0;
            if (s0 > 0.f && s0 == m0) nb |= 1u;
            if (s1 > 0.f && s1 == m1) nb |= 2u;
            if (s2 > 0.f && s2 == m2) nb |= 4u;
            if (s3 > 0.f && s3 == m3) nb |= 8u;
            *(float4*)&ring[myz & 15][u0] = make_float4(m0, m1, m2, m3);
            semi[myz & 15][q] = (unsigned char)nb;
        }
        // ---- prefetch raw rows z+4, z+5 ----
        {
            int zz = z + 4 + h;
            int yy = zz < 0 ? 0 : (zz > H - 1 ? H - 1 : zz);
            const float* rp = img + (size_t)yy * S;
            int slot = zz & 7;
            if (xfast) {
                if (q < 62)
                    *(float4*)&raw[slot][q * 4] = __ldg((const float4*)(rp + xb - 12 + q * 4));
            } else {
                for (int i = q; i < 248; i += 64) {
                    int x = xb - 12 + i;
                    x = x < 0 ? 0 : (x > W - 1 ? W - 1 : x);
                    raw[slot][i] = __ldg(rp + x);
                }
            }
        }
        __syncthreads();

        // ---- emission of ready rows ----
        int eHi = nextE;
        while (eHi < yend) {
            int need = eHi + 7; if (need > H - 1) need = H - 1;
            if (need <= lastz) ++eHi; else break;
        }
        for (int e = nextE + h; e < eHi; e += 2) {
            if (q < 56) {
                int u0 = q * 4;
                unsigned nbq = semi[e & 15][q];
                if (nbq) {
                    int rr0 = e - 7; rr0 = rr0 < 0 ? 0 : rr0;
                    float4 cm = *(const float4*)&ring[rr0 & 15][u0];
                    #pragma unroll
                    for (int j = 1; j < 15; ++j) {
                        int rr = e - 7 + j;
                        rr = rr < 0 ? 0 : (rr > H - 1 ? H - 1 : rr);
                        cm = f4max(cm, *(const float4*)&ring[rr & 15][u0]);
                    }
                    float4 ctr = *(const float4*)&ring[e & 15][u0];
                    const float* cp = (const float*)&ctr;
                    const float* mp = (const float*)&cm;
                    int x0 = xb + u0;
                    #pragma unroll
                    for (int c = 0; c < 4; ++c) {
                        if (((nbq >> c) & 1u) && cp[c] == mp[c]) {
                            unsigned sbits = __float_as_uint(cp[c]) | 0x80000000u;
                            int pix = e * W + x0 + c;
                            u64 key = ((u64)sbits << 26) | ((u64)(5 - l) << 23)
                                    | (u64)(0x7FFFFF - pix);
                            int pos = atomicAdd(&g_cnt[l], 1);
                            if (pos < CAP) g_cand[(size_t)l * CAP + pos] = key;
                        }
                    }
                }
            }
        }
        nextE = eHi;
    }
}

// ---------------------------------------------------------------------------
// Hierarchical per-level select (block l -> level l): 12-bit histogram levels
// with PARALLEL suffix-scan digit search, one classify pass, exact boundary-bin
// bitonic sort. hist/buf overlaid.
__global__ void __launch_bounds__(1024) k_select6()
{
    __shared__ __align__(16) HistBuf hb;
    __shared__ int s_scan[1024];
    __shared__ u64 s_pref;
    __shared__ int s_kk, s_binCnt, s_bufCnt;
    int l   = blockIdx.x;
    int tid = threadIdx.x;
    const u64* src = g_cand + (size_t)l * CAP;
    int k   = c_k[l];
    int cnt = g_cnt[l];
    if (cnt > CAP) cnt = CAP;

    if (cnt <= k) {
        for (int i = tid; i < cnt; i += 1024) {
            int p = atomicAdd(&g_cnt[6], 1);
            g_pool[p] = src[i];
        }
        return;
    }

    if (tid == 0) { s_pref = 0ull; s_kk = k; }
    int shift = 52;
    for (;;) {
        for (int i = tid; i < 4096; i += 1024) hb.hist[i] = 0;
        __syncthreads();
        u64 pref = s_pref;
        for (int i = tid; i < cnt; i += 1024) {
            u64 key = src[i];
            bool m = (shift == 52) ? true : ((key >> (shift + 12)) == pref);
            if (m) atomicAdd(&hb.hist[(int)((key >> shift) & 4095)], 1);
        }
        __syncthreads();
        int kk_cur = s_kk;
        int jbase = tid * 4;
        int part = 0;
        #pragma unroll
        for (int qq = 0; qq < 4; ++qq) part += hb.hist[4095 - (jbase + qq)];
        s_scan[tid] = part;
        __syncthreads();
        for (int off = 1; off < 1024; off <<= 1) {
            int v = s_scan[tid];
            int add = (tid >= off) ? s_scan[tid - off] : 0;
            __syncthreads();
            s_scan[tid] = v + add;
            __syncthreads();
        }
        int incl = s_scan[tid];
        int base = incl - part;
        if (base < kk_cur && kk_cur <= incl) {
            int cum = base;
            #pragma unroll
            for (int qq = 0; qq < 4; ++qq) {
                int d = 4095 - (jbase + qq);
                int hh = hb.hist[d];
                cum += hh;
                if (cum >= kk_cur) {
                    s_kk = kk_cur - (cum - hh);
                    s_binCnt = hh;
                    s_pref = (s_pref << 12) | (u64)d;
                    break;
                }
            }
        }
        __syncthreads();
        if (s_binCnt <= 2048 || shift == 4) break;
        shift -= 12;
    }
    int kRem = s_kk;
    u64 pref = s_pref;
    if (tid == 0) s_bufCnt = 0;
    __syncthreads();
    hb.buf[tid] = 0ull; hb.buf[tid + 1024] = 0ull;
    __syncthreads();

    for (int i = tid; i < cnt; i += 1024) {
        u64 key = src[i];
        u64 hi = key >> shift;
        if (hi > pref) {
            int p = atomicAdd(&g_cnt[6], 1);
            g_pool[p] = key;
        } else if (hi == pref) {
            int p = atomicAdd(&s_bufCnt, 1);
            if (p < 2048) hb.buf[p] = key;
        }
    }
    __syncthreads();

    for (int ksz = 2; ksz <= 2048; ksz <<= 1) {
        for (int j = ksz >> 1; j > 0; j >>= 1) {
            #pragma unroll
            for (int half = 0; half < 2; ++half) {
                int i = tid + half * 1024;
                int ixj = i ^ j;
                if (ixj > i) {
                    u64 a = hb.buf[i], b = hb.buf[ixj];
                    bool asc = ((i & ksz) == 0);
                    if (asc ? (a > b) : (a < b)) { hb.buf[i] = b; hb.buf[ixj] = a; }
                }
            }
            __syncthreads();
        }
    }
    for (int i = tid; i < kRem; i += 1024) {
        int p = atomicAdd(&g_cnt[6], 1);
        g_pool[p] = hb.buf[2047 - i];
    }
}

// ---------------------------------------------------------------------------
// Final: hierarchical select of top 2048 from pool (parallel digit search),
// full sort, decode, emit. hist/buf overlaid to stay under 48KB static smem.
__global__ void __launch_bounds__(1024) k_final(float* __restrict__ out, int out_size)
{
    __shared__ __align__(16) HistBuf hb;
    __shared__ u64 s[2048];
    __shared__ int s_scan[1024];
    __shared__ u64 s_pref;
    __shared__ int s_kk, s_binCnt, s_bufCnt, s_aboveCnt;
    int tid = threadIdx.x;
    int cnt = g_cnt[6];
    if (cnt > 12288) cnt = 12288;
    const int K = 2048;

    s[tid] = 0ull; s[tid + 1024] = 0ull;
    if (cnt <= K) {
        __syncthreads();
        for (int i = tid; i < cnt; i += 1024) s[i] = g_pool[i];
        __syncthreads();
    } else {
        if (tid == 0) { s_pref = 0ull; s_kk = K; s_aboveCnt = 0; s_bufCnt = 0; }
        int shift = 52;
        for (;;) {
            for (int i = tid; i < 4096; i += 1024) hb.hist[i] = 0;
            __syncthreads();
            u64 pref = s_pref;
            for (int i = tid; i < cnt; i += 1024) {
                u64 key = g_pool[i];
                bool m = (shift == 52) ? true : ((key >> (shift + 12)) == pref);
                if (m) atomicAdd(&hb.hist[(int)((key >> shift) & 4095)], 1);
            }
            __syncthreads();
            int kk_cur = s_kk;
            int jbase = tid * 4;
            int part = 0;
            #pragma unroll
            for (int qq = 0; qq < 4; ++qq) part += hb.hist[4095 - (jbase + qq)];
            s_scan[tid] = part;
            __syncthreads();
            for (int off = 1; off < 1024; off <<= 1) {
                int v = s_scan[tid];
                int add = (tid >= off) ? s_scan[tid - off] : 0;
                __syncthreads();
                s_scan[tid] = v + add;
                __syncthreads();
            }
            int incl = s_scan[tid];
            int base = incl - part;
            if (base < kk_cur && kk_cur <= incl) {
                int cum = base;
                #pragma unroll
                for (int qq = 0; qq < 4; ++qq) {
                    int d = 4095 - (jbase + qq);
                    int hh = hb.hist[d];
                    cum += hh;
                    if (cum >= kk_cur) {
                        s_kk = kk_cur - (cum - hh);
                        s_binCnt = hh;
                        s_pref = (s_pref << 12) | (u64)d;
                        break;
                    }
                }
            }
            __syncthreads();
            if (s_binCnt <= 2048 || shift == 4) break;
            shift -= 12;
        }
        int kRem = s_kk;
        u64 pref = s_pref;
        __syncthreads();
        hb.buf[tid] = 0ull; hb.buf[tid + 1024] = 0ull;
        __syncthreads();
        for (int i = tid; i < cnt; i += 1024) {
            u64 key = g_pool[i];
            u64 hi = key >> shift;
            if (hi > pref) {
                int p = atomicAdd(&s_aboveCnt, 1);
                s[p] = key;
            } else if (hi == pref) {
                int p = atomicAdd(&s_bufCnt, 1);
                if (p < 2048) hb.buf[p] = key;
            }
        }
        __syncthreads();
        for (int ksz = 2; ksz <= 2048; ksz <<= 1) {
            for (int j = ksz >> 1; j > 0; j >>= 1) {
                #pragma unroll
                for (int half = 0; half < 2; ++half) {
                    int i = tid + half * 1024;
                    int ixj = i ^ j;
                    if (ixj > i) {
                        u64 a = hb.buf[i], b = hb.buf[ixj];
                        bool asc = ((i & ksz) == 0);
                        if (asc ? (a > b) : (a < b)) { hb.buf[i] = b; hb.buf[ixj] = a; }
                    }
                }
                __syncthreads();
            }
        }
        int above = s_aboveCnt;   // == K - kRem
        for (int i = tid; i < kRem; i += 1024) s[above + i] = hb.buf[2047 - i];
        __syncthreads();
    }

    for (int ksz = 2; ksz <= 2048; ksz <<= 1) {
        for (int j = ksz >> 1; j > 0; j >>= 1) {
            #pragma unroll
            for (int half = 0; half < 2; ++half) {
                int i = tid + half * 1024;
                int ixj = i ^ j;
                if (ixj > i) {
                    u64 a = s[i], b = s[ixj];
                    bool asc = ((i & ksz) == 0);
                    if (asc ? (a > b) : (a < b)) { s[i] = b; s[ixj] = a; }
                }
            }
            __syncthreads();
        }
    }

    bool haveL = (out_size >= 12288);
    bool haveR = (out_size >= 14336) || (out_size < 12288);
    int rbase  = (out_size >= 14336) ? 12288 : 0;
    for (int r = tid; r < 2048; r += 1024) {
        u64 key = s[2047 - r];
        int pix = 0x7FFFFF - (int)(key & 0x7FFFFF);
        int lvl = 5 - (int)((key >> 23) & 7);
        float scv = __uint_as_float((unsigned)(key >> 26) & 0x7FFFFFFFu);
        int Wl = c_W[lvl];
        int py = pix / Wl, px = pix - py * Wl;
        float f  = c_fact[lvl], sg = c_scal[lvl];
        float fx = __fmul_rn((float)px, f);
        float fy = __fmul_rn((float)py, f);
        if (haveL) {
            float* L = out + (size_t)r * 6;
            L[0] = sg; L[1] = 0.f; L[2] = fx;
            L[3] = 0.f; L[4] = sg; L[5] = fy;
        }
        if (haveR) out[rbase + r] = scv;
    }
}

// ---------------------------------------------------------------------------
extern "C" void kernel_launch(void* const* d_in, const int* in_sizes, int n_in,
                              void* d_out, int out_size)
{
    const float* img = (const float*)d_in[0];
    const float* cw  = (const float*)d_in[1];
    const float* cb  = (const float*)d_in[2];
    float* out = (float*)d_out;

    void *p_up, *p_i2, *p_i3, *p_i4, *p_i5, *p_bB;
    cudaGetSymbolAddress(&p_up, g_imgup);
    cudaGetSymbolAddress(&p_i2, g_img2);
    cudaGetSymbolAddress(&p_i3, g_img3);
    cudaGetSymbolAddress(&p_i4, g_img4);
    cudaGetSymbolAddress(&p_i5, g_img5);
    cudaGetSymbolAddress(&p_bB, g_blurB);
    float *imgup=(float*)p_up, *img2=(float*)p_i2, *img3=(float*)p_i3,
          *img4=(float*)p_i4, *img5=(float*)p_i5, *bB=(float*)p_bB;

    // gaussian 5-tap, sigma=1 (identical host math to passing kernels)
    float gx[5] = {4.f, 1.f, 0.f, 1.f, 4.f};
    float g[5], gs = 0.f;
    for (int i = 0; i < 5; ++i) { g[i] = expf(-gx[i] * 0.5f); gs += g[i]; }
    for (int i = 0; i < 5; ++i) g[i] /= gs;

    k_init<<<26, 256>>>();

    // level 0: upscale 2048 -> 2896 (table at offset 0)
    k_resize2<<<dim3(3, 2896), 256>>>(img, 2048, imgup, 2896, 2896, 0);

    // pyrdown chain: blur (fused V+H) then table-driven resize
    k_blurVH<<<dim3(5, 256), 128>>>(img, bB, 2048, 2048, 2048, g[0], g[1], g[2]);
    k_resize2<<<dim3(2, 1448), 256>>>(bB, 2048, img2, 1448, 1448, 2896);

    k_blurVH<<<dim3(3, 181), 128>>>(img2, bB, 1448, 1448, 1448, g[0], g[1], g[2]);
    k_resize2<<<dim3(1, 1023), 256>>>(bB, 1448, img3, 1024, 1023, 4344);

    k_blurVH<<<dim3(3, 128), 128>>>(img3, bB, 1024, 1023, 1023, g[0], g[1], g[2]);
    k_resize2<<<dim3(1, 723), 256>>>(bB, 1024, img4, 724, 723, 5367);

    k_blurVH<<<dim3(2, 91), 128>>>(img4, bB, 724, 723, 723, g[0], g[1], g[2]);
    k_resize2<<<dim3(1, 511), 256>>>(bB, 724, img5, 512, 511, 6090);

    // fused detection across all 6 levels
    k_fused<<<619, 128>>>(img, cw, cb);

    // selection
    k_select6<<<6, 1024>>>();
    k_final<<<1, 1024>>>(out, out_size);
}

// round 15
// speedup vs baseline: 1.1097x; 1.1097x over previous
#include <cuda_runtime.h>
#include <math.h>
#include <stdint.h>

typedef unsigned long long u64;

#define CAP 65536

// ---- device scratch (no allocations allowed) ----
__device__ float    g_imgup[2896*2896];
__device__ float    g_img2 [1448*1448];
__device__ float    g_img3 [1024*1023];
__device__ float    g_img4 [724*723];
__device__ float    g_img5 [512*511];
__device__ float    g_blurB[2048*2048];
__device__ float    g_rmax [16510464];
__device__ unsigned g_mask [518784];
__device__ float4   g_rtab [6601];
__device__ u64      g_cand[6*CAP];
__device__ u64      g_pool[12288];
__device__ int      g_cnt[8];   // [0..5]=per-level cand count, [6]=pool

__constant__ int   c_W[6]    = {2896,2048,1448,1023,723,511};
__constant__ int   c_S[6]    = {2896,2048,1448,1024,724,512};
__constant__ int   c_off[6]  = {0, 8386816, 12581120, 14677824, 15725376, 16248832};
__constant__ int   c_mS[6]   = {91,64,46,32,23,16};
__constant__ int   c_moff[6] = {0, 263536, 394608, 461216, 493952, 510581};
__constant__ float c_fact[6] = {(float)(2048.0/2896.0), 1.0f, (float)(2048.0/1448.0),
                                (float)(2048.0/1023.0), (float)(2048.0/723.0), (float)(2048.0/511.0)};
__constant__ float c_scal[6] = {(float)(2048.0/2896.0*22.0), 22.0f, (float)(2048.0/1448.0*22.0),
                                (float)(2048.0/1023.0*22.0), (float)(2048.0/723.0*22.0), (float)(2048.0/511.0*22.0)};
__constant__ int   c_k[6]    = {1040,1560,1820,1950,2015,2047};

// convnms tile tables: blocks/level = ceil(W/512) x ceil(W/8)
__constant__ int c_cumNC[6] = {0, 2172, 3196, 3739, 3995, 4177};   // total 4241
__constant__ int c_bx[6]    = {6, 4, 3, 2, 2, 1};
// colcheck (32-row chunked) tables: blocks/level = ceil(W/512) x ceil(W/32)
__constant__ int c_cumCC[6] = {0, 546, 802, 940, 1004, 1050};      // total 1066

// resize-weight-table layout
__constant__ int   c_toff[5] = {0, 2896, 4344, 5367, 6090};        // total 6601
__constant__ int   c_rsw[5]  = {2048, 2048, 1448, 1023, 723};
__constant__ float c_rinv[5] = {(float)(2048.0/2896.0), (float)(2048.0/1448.0),
                                (float)(1448.0/1023.0), (float)(1023.0/723.0),
                                (float)(723.0/511.0)};

union HistBuf { int hist[4096]; u64 buf[2048]; };

__device__ __forceinline__ float4 f4max(float4 a, float4 b)
{
    return make_float4(fmaxf(a.x,b.x), fmaxf(a.y,b.y), fmaxf(a.z,b.z), fmaxf(a.w,b.w));
}

// ---------------------------------------------------------------------------
// init: zero counters + build resize weight tables (bit-identical arithmetic
// to the per-pixel resize math of the R5 passing kernel).
__global__ void __launch_bounds__(256) k_init()
{
    int idx = blockIdx.x * 256 + threadIdx.x;
    if (idx < 8) g_cnt[idx] = 0;
    if (idx >= 6601) return;
    int r = 4;
    while (idx < c_toff[r]) --r;
    int d  = idx - c_toff[r];
    int sw = c_rsw[r];
    float invs = c_rinv[r];

    float sx = __fadd_rn(__fmul_rn(__fadd_rn((float)d, 0.5f), invs), -0.5f);
    int j0 = (int)floorf(sx), j1 = j0 + 1;
    float w0 = __fadd_rn(1.0f, -__fadd_rn(sx, -(float)j0));
    float w1 = __fadd_rn(1.0f, -__fadd_rn((float)j1, -sx));
    bool v0 = (j0 >= 0), v1 = (j1 <= sw - 1);
    int C0 = v0 ? j0 : 0, C1 = v1 ? j1 : sw - 1;
    float n0, n1;
    if (v0 && v1) {
        float tot = __fadd_rn(w0, w1);
        n0 = __fdiv_rn(w0, tot); n1 = __fdiv_rn(w1, tot);
    } else if (v0) { n0 = 1.0f; n1 = 0.0f; }
    else           { n0 = 0.0f; n1 = 1.0f; }
    g_rtab[idx] = make_float4(n0, n1, __int_as_float(C0), __int_as_float(C1));
}

// ---------------------------------------------------------------------------
// Table-driven bilinear resize (jax half-pixel semantics baked into tables).
__global__ void __launch_bounds__(256) k_resize2(const float* __restrict__ in, int sIn,
                         float* __restrict__ dst, int sOut, int dw, int tab)
{
    int dy  = blockIdx.y;
    int dx0 = (blockIdx.x * 256 + threadIdx.x) * 4;
    if (dx0 >= dw) return;

    float4 ye = g_rtab[tab + dy];
    float n0y = ye.x, n1y = ye.y;
    const float* r0 = in + (size_t)__float_as_int(ye.z) * sIn;
    const float* r1 = in + (size_t)__float_as_int(ye.w) * sIn;

    float res[4];
    int nn = dw - dx0; if (nn > 4) nn = 4;
    #pragma unroll
    for (int c = 0; c < 4; ++c) {
        if (c >= nn) break;
        float4 xe = g_rtab[tab + dx0 + c];
        float n0x = xe.x, n1x = xe.y;
        int cx0 = __float_as_int(xe.z), cx1 = __float_as_int(xe.w);
        float p00 = __ldg(r0 + cx0), p01 = __ldg(r0 + cx1);
        float p10 = __ldg(r1 + cx0), p11 = __ldg(r1 + cx1);
        float c0 = __fadd_rn(__fmul_rn(n0y, p00), __fmul_rn(n1y, p10));
        float c1 = __fadd_rn(__fmul_rn(n0y, p01), __fmul_rn(n1y, p11));
        res[c] = __fadd_rn(__fmul_rn(n0x, c0), __fmul_rn(n1x, c1));
    }
    float* orow = dst + (size_t)dy * sOut;
    if (nn == 4) *(float4*)(orow + dx0) = make_float4(res[0], res[1], res[2], res[3]);
    else for (int c = 0; c < nn; ++c) orow[dx0 + c] = res[c];
}

// ---------------------------------------------------------------------------
__device__ __forceinline__ int reflect_i(int i, int n)
{
    if (i < 0) return -i;
    if (i >= n) return 2 * n - 2 - i;
    return i;
}

// Fused separable 5-tap gaussian blur (reflect): V in registers, H via smem.
__global__ void __launch_bounds__(128) k_blurVH(const float* __restrict__ in,
        float* __restrict__ out, int S, int W, int H,
        float g0, float g1, float g2)
{
    __shared__ __align__(16) float sv[8][512];
    int t  = threadIdx.x;
    int xb = blockIdx.x * 504;
    int yb = blockIdx.y * 8;
    int xg = xb - 4 + t * 4;

    float4 raw[12];
    bool fast = (xg >= 0) && (xg + 4 <= W);
    #pragma unroll
    for (int r = 0; r < 12; ++r) {
        const float* rowp = in + (size_t)reflect_i(yb - 2 + r, H) * S;
        if (fast) {
            raw[r] = __ldg((const float4*)(rowp + xg));
        } else {
            float t0 = __ldg(rowp + reflect_i(xg,     W));
            float t1 = __ldg(rowp + reflect_i(xg + 1, W));
            float t2 = __ldg(rowp + reflect_i(xg + 2, W));
            float t3 = __ldg(rowp + reflect_i(xg + 3, W));
            raw[r] = make_float4(t0, t1, t2, t3);
        }
    }
    #pragma unroll
    for (int r = 0; r < 8; ++r) {
        float4 a = raw[r], b = raw[r+1], c = raw[r+2], d = raw[r+3], e = raw[r+4];
        float4 vb;
        vb.x = fmaf(g0, e.x, fmaf(g1, d.x, fmaf(g2, c.x, fmaf(g1, b.x, g0 * a.x))));
        vb.y = fmaf(g0, e.y, fmaf(g1, d.y, fmaf(g2, c.y, fmaf(g1, b.y, g0 * a.y))));
        vb.z = fmaf(g0, e.z, fmaf(g1, d.z, fmaf(g2, c.z, fmaf(g1, b.z, g0 * a.z))));
        vb.w = fmaf(g0, e.w, fmaf(g1, d.w, fmaf(g2, c.w, fmaf(g1, b.w, g0 * a.w))));
        *(float4*)&sv[r][t * 4] = vb;
    }
    __syncthreads();
    if (t >= 126) return;
    int xo = xb + t * 4;
    if (xo >= W) return;
    #pragma unroll
    for (int r = 0; r < 8; ++r) {
        int yo = yb + r;
        if (yo >= H) break;
        float v[12];
        #pragma unroll
        for (int q = 0; q < 3; ++q) {
            float4 a = *(float4*)&sv[r][t * 4 + q * 4];
            v[q*4] = a.x; v[q*4+1] = a.y; v[q*4+2] = a.z; v[q*4+3] = a.w;
        }
        float res[4];
        #pragma unroll
        for (int c = 0; c < 4; ++c) {
            res[c] = fmaf(g0, v[c + 6], fmaf(g1, v[c + 5],
                     fmaf(g2, v[c + 4], fmaf(g1, v[c + 3], g0 * v[c + 2]))));
        }
        float* orow = out + (size_t)yo * S;
        if (xo + 4 <= W) {
            *(float4*)(orow + xo) = make_float4(res[0], res[1], res[2], res[3]);
        } else {
            for (int c = 0; c < 4; ++c) if (xo + c < W) orow[xo + c] = res[c];
        }
    }
}

// ---------------------------------------------------------------------------
// Merged (multi-level) 8-row-tile fused conv + border-mask + row-max + semi-mask.
// Identical math to the 342us kernel; 'base' selects the global tile range so
// levels 0-1 can be launched before the rest of the pyramid exists.
__global__ void __launch_bounds__(160) k_convnms(const float* __restrict__ imgOrig,
        const float* __restrict__ wp, const float* __restrict__ bp, int base)
{
    __shared__ float swt[25];
    __shared__ float sbv;
    __shared__ __align__(16) float raw[12][536];
    __shared__ __align__(16) float sc[2][528];
    __shared__ unsigned char nib[8][128];
    int t = threadIdx.x;
    if (t < 25) swt[t] = __ldg(wp + t);
    if (t == 31) sbv = __ldg(bp);

    int bid = blockIdx.x + base;
    int l = 5;
    while (bid < c_cumNC[l]) --l;
    int rem  = bid - c_cumNC[l];
    int bx   = c_bx[l];
    int yblk = rem / bx;
    int xblk = rem - yblk * bx;
    int W = c_W[l], H = W, S = c_S[l];
    const float* img;
    switch (l) {
        case 0: img = g_imgup; break;
        case 1: img = imgOrig; break;
        case 2: img = g_img2;  break;
        case 3: img = g_img3;  break;
        case 4: img = g_img4;  break;
        default: img = g_img5; break;
    }
    int y0 = yblk * 8, xb = xblk * 512;

    bool xfast = (xb >= 12) && (xb + 524 <= W);
    #pragma unroll
    for (int r = 0; r < 12; ++r) {
        int yy = y0 - 2 + r;
        yy = yy < 0 ? 0 : (yy > H - 1 ? H - 1 : yy);
        const float* rp = img + (size_t)yy * S;
        if (xfast) {
            if (t < 134)
                *(float4*)&raw[r][t * 4] = __ldg((const float4*)(rp + xb - 12 + t * 4));
        } else {
            for (int i = t; i < 536; i += 160) {
                int x = xb - 12 + i;
                x = x < 0 ? 0 : (x > W - 1 ? W - 1 : x);
                raw[r][i] = __ldg(rp + x);
            }
        }
    }
    __syncthreads();

    float wreg[25];
    float breg = 0.f;
    if (t < 132) {
        #pragma unroll
        for (int i = 0; i < 25; ++i) wreg[i] = swt[i];
        breg = sbv;
    }
    int tc = t * 4;
    float* rbase = g_rmax + c_off[l];

    #pragma unroll
    for (int pr = 0; pr < 4; ++pr) {
        int rA = pr * 2;
        if (t < 132) {
            float a0[4], a1[4];
            #pragma unroll
            for (int c = 0; c < 4; ++c) { a0[c] = breg; a1[c] = breg; }
            #pragma unroll
            for (int z = 0; z < 6; ++z) {
                float4 A = *(const float4*)&raw[rA + z][tc];
                float4 B = *(const float4*)&raw[rA + z][tc + 4];
                float4 C = *(const float4*)&raw[rA + z][tc + 8];
                float v[12] = {A.x,A.y,A.z,A.w, B.x,B.y,B.z,B.w, C.x,C.y,C.z,C.w};
                if (z <= 4) {
                    const float* wr = &wreg[z * 5];
                    #pragma unroll
                    for (int c = 0; c < 4; ++c) {
                        a0[c] = fmaf(wr[0], v[2 + c], a0[c]);
                        a0[c] = fmaf(wr[1], v[3 + c], a0[c]);
                        a0[c] = fmaf(wr[2], v[4 + c], a0[c]);
                        a0[c] = fmaf(wr[3], v[5 + c], a0[c]);
                        a0[c] = fmaf(wr[4], v[6 + c], a0[c]);
                    }
                }
                if (z >= 1) {
                    const float* wr = &wreg[(z - 1) * 5];
                    #pragma unroll
                    for (int c = 0; c < 4; ++c) {
                        a1[c] = fmaf(wr[0], v[2 + c], a1[c]);
                        a1[c] = fmaf(wr[1], v[3 + c], a1[c]);
                        a1[c] = fmaf(wr[2], v[4 + c], a1[c]);
                        a1[c] = fmaf(wr[3], v[5 + c], a1[c]);
                        a1[c] = fmaf(wr[4], v[6 + c], a1[c]);
                    }
                }
            }
            int xg = xb - 8 + tc;
            #pragma unroll
            for (int h = 0; h < 2; ++h) {
                int yv = y0 + rA + h;
                bool rowok = (yv >= 15 && yv < H - 15);
                float* ap = h ? a1 : a0;
                float4 o;
                o.x = (rowok && xg + 0 >= 15 && xg + 0 < W - 15) ? ap[0] : 0.f;
                o.y = (rowok && xg + 1 >= 15 && xg + 1 < W - 15) ? ap[1] : 0.f;
                o.z = (rowok && xg + 2 >= 15 && xg + 2 < W - 15) ? ap[2] : 0.f;
                o.w = (rowok && xg + 3 >= 15 && xg + 3 < W - 15) ? ap[3] : 0.f;
                *(float4*)&sc[h][tc] = o;
            }
        }
        __syncthreads();

        if (t < 128) {
            #pragma unroll
            for (int h = 0; h < 2; ++h) {
                int r = rA + h;
                float4 q0 = *(const float4*)&sc[h][tc];
                float4 q1 = *(const float4*)&sc[h][tc + 4];
                float4 q2 = *(const float4*)&sc[h][tc + 8];
                float4 q3 = *(const float4*)&sc[h][tc + 12];
                float4 q4 = *(const float4*)&sc[h][tc + 16];
                float f[20] = {q0.x,q0.y,q0.z,q0.w, q1.x,q1.y,q1.z,q1.w,
                               q2.x,q2.y,q2.z,q2.w, q3.x,q3.y,q3.z,q3.w,
                               q4.x,q4.y,q4.z,q4.w};
                float run = f[15];
                #pragma unroll
                for (int i = 14; i >= 5; --i) run = fmaxf(run, f[i]);
                float suf4 = fmaxf(run, f[4]);
                float suf3 = fmaxf(suf4, f[3]);
                float suf2 = fmaxf(suf3, f[2]);
                float suf1 = fmaxf(suf2, f[1]);
                float r0 = suf1;
                float run2 = f[16];
                float r1 = fmaxf(suf2, run2);
                run2 = fmaxf(run2, f[17]);
                float r2 = fmaxf(suf3, run2);
                run2 = fmaxf(run2, f[18]);
                float r3 = fmaxf(suf4, run2);
                float s0 = f[8], s1 = f[9], s2 = f[10], s3 = f[11];
                unsigned nb = 0;
                if (s0 > 0.f && s0 == r0) nb |= 1u;
                if (s1 > 0.f && s1 == r1) nb |= 2u;
                if (s2 > 0.f && s2 == r2) nb |= 4u;
                if (s3 > 0.f && s3 == r3) nb |= 8u;
                nib[r][t] = (unsigned char)nb;
                int yv = y0 + r;
                int x0 = xb + tc;
                if (yv < H && x0 < S)
                    *(float4*)(rbase + (size_t)yv * S + x0) = make_float4(r0, r1, r2, r3);
            }
        }
        __syncthreads();
    }

    if (t < 128) {
        int r = t >> 4, w = t & 15;
        unsigned word = 0;
        #pragma unroll
        for (int q = 0; q < 8; ++q)
            word |= ((unsigned)nib[r][w * 8 + q]) << (q * 4);
        int yv = y0 + r;
        int wi = xblk * 16 + w;
        if (yv < H && wi < c_mS[l])
            g_mask[c_moff[l] + yv * c_mS[l] + wi] = word;
    }
}

// ---------------------------------------------------------------------------
// Chunked column-max check: 32 output rows per block (4 chunks of 8), register
// window shifted between chunks. Max/emission arithmetic identical.
__global__ void __launch_bounds__(128) k_colcheck()
{
    int bid = blockIdx.x;
    int l = 5;
    while (bid < c_cumCC[l]) --l;
    int rem  = bid - c_cumCC[l];
    int bx   = c_bx[l];
    int yblk = rem / bx;
    int xblk = rem - yblk * bx;
    int W = c_W[l], H = W, S = c_S[l];
    const float* rmax = g_rmax + c_off[l];
    const unsigned* mrow = g_mask + c_moff[l];
    int mS = c_mS[l];

    int x4 = xblk * 512 + threadIdx.x * 4;
    if (x4 >= W) return;
    int y0 = yblk * 32;

    float4 v[22];
    #pragma unroll
    for (int j = 0; j < 22; ++j) {
        int yy = y0 - 7 + j;
        yy = yy < 0 ? 0 : (yy > H - 1 ? H - 1 : yy);
        v[j] = __ldg((const float4*)(rmax + (size_t)yy * S + x4));
    }

    #pragma unroll
    for (int ch = 0; ch < 4; ++ch) {
        int yb = y0 + ch * 8;
        if (yb >= H) break;

        unsigned nb[8]; unsigned any = 0;
        #pragma unroll
        for (int o = 0; o < 8; ++o) {
            int y = yb + o;
            unsigned m = (y < H) ? __ldg(mrow + y * mS + (x4 >> 5)) : 0u;
            nb[o] = (m >> (x4 & 31)) & 15u;
            any |= nb[o];
        }
        if (any) {
            float4 pre[8];
            float4 run = v[14];
            #pragma unroll
            for (int j = 13; j >= 0; --j) {
                run = f4max(run, v[j]);
                if (j <= 7) pre[j] = run;
            }
            float4 run2 = v[15];
            #pragma unroll
            for (int o = 0; o < 8; ++o) {
                int y = yb + o;
                if (y >= H) break;
                float4 m;
                if (o == 0) m = pre[0];
                else {
                    if (o >= 2) run2 = f4max(run2, v[o + 14]);
                    m = f4max(pre[o], run2);
                }
                if (!nb[o]) continue;
                float4 ctr = v[o + 7];
                const float* sp = (const float*)&ctr;
                const float* mp = (const float*)&m;
                #pragma unroll
                for (int cc = 0; cc < 4; ++cc) {
                    if (!((nb[o] >> cc) & 1u)) continue;
                    int x = x4 + cc;
                    float s = sp[cc];
                    if (x < W && s == mp[cc]) {
                        unsigned sbits = __float_as_uint(s) | 0x80000000u;
                        int pix = y * W + x;
                        u64 key = ((u64)sbits << 26) | ((u64)(5 - l) << 23)
                                | (u64)(0x7FFFFF - pix);
                        int pos = atomicAdd(&g_cnt[l], 1);
                        if (pos < CAP) g_cand[(size_t)l * CAP + pos] = key;
                    }
                }
            }
        }
        if (ch < 3) {
            #pragma unroll
            for (int j = 0; j < 14; ++j) v[j] = v[j + 8];
            #pragma unroll
            for (int j = 14; j < 22; ++j) {
                int yy = yb + 1 + j;         // next chunk base (yb+8) - 7 + j
                yy = yy < 0 ? 0 : (yy > H - 1 ? H - 1 : yy);
                v[j] = __ldg((const float4*)(rmax + (size_t)yy * S + x4));
            }
        }
    }
}

// ---------------------------------------------------------------------------
// Hierarchical per-level select (block l -> level l): 12-bit histogram levels
// with PARALLEL suffix-scan digit search, one classify pass, exact boundary-bin
// bitonic sort. hist/buf overlaid.
__global__ void __launch_bounds__(1024) k_select6()
{
    __shared__ __align__(16) HistBuf hb;
    __shared__ int s_scan[1024];
    __shared__ u64 s_pref;
    __shared__ int s_kk, s_binCnt, s_bufCnt;
    int l   = blockIdx.x;
    int tid = threadIdx.x;
    const u64* src = g_cand + (size_t)l * CAP;
    int k   = c_k[l];
    int cnt = g_cnt[l];
    if (cnt > CAP) cnt = CAP;

    if (cnt <= k) {
        for (int i = tid; i < cnt; i += 1024) {
            int p = atomicAdd(&g_cnt[6], 1);
            g_pool[p] = src[i];
        }
        return;
    }

    if (tid == 0) { s_pref = 0ull; s_kk = k; }
    int shift = 52;
    for (;;) {
        for (int i = tid; i < 4096; i += 1024) hb.hist[i] = 0;
        __syncthreads();
        u64 pref = s_pref;
        for (int i = tid; i < cnt; i += 1024) {
            u64 key = src[i];
            bool m = (shift == 52) ? true : ((key >> (shift + 12)) == pref);
            if (m) atomicAdd(&hb.hist[(int)((key >> shift) & 4095)], 1);
        }
        __syncthreads();
        int kk_cur = s_kk;
        int jbase = tid * 4;
        int part = 0;
        #pragma unroll
        for (int qq = 0; qq < 4; ++qq) part += hb.hist[4095 - (jbase + qq)];
        s_scan[tid] = part;
        __syncthreads();
        for (int off = 1; off < 1024; off <<= 1) {
            int v = s_scan[tid];
            int add = (tid >= off) ? s_scan[tid - off] : 0;
            __syncthreads();
            s_scan[tid] = v + add;
            __syncthreads();
        }
        int incl = s_scan[tid];
        int base = incl - part;
        if (base < kk_cur && kk_cur <= incl) {
            int cum = base;
            #pragma unroll
            for (int qq = 0; qq < 4; ++qq) {
                int d = 4095 - (jbase + qq);
                int hh = hb.hist[d];
                cum += hh;
                if (cum >= kk_cur) {
                    s_kk = kk_cur - (cum - hh);
                    s_binCnt = hh;
                    s_pref = (s_pref << 12) | (u64)d;
                    break;
                }
            }
        }
        __syncthreads();
        if (s_binCnt <= 2048 || shift == 4) break;
        shift -= 12;
    }
    int kRem = s_kk;
    u64 pref = s_pref;
    if (tid == 0) s_bufCnt = 0;
    __syncthreads();
    hb.buf[tid] = 0ull; hb.buf[tid + 1024] = 0ull;
    __syncthreads();

    for (int i = tid; i < cnt; i += 1024) {
        u64 key = src[i];
        u64 hi = key >> shift;
        if (hi > pref) {
            int p = atomicAdd(&g_cnt[6], 1);
            g_pool[p] = key;
        } else if (hi == pref) {
            int p = atomicAdd(&s_bufCnt, 1);
            if (p < 2048) hb.buf[p] = key;
        }
    }
    __syncthreads();

    for (int ksz = 2; ksz <= 2048; ksz <<= 1) {
        for (int j = ksz >> 1; j > 0; j >>= 1) {
            #pragma unroll
            for (int half = 0; half < 2; ++half) {
                int i = tid + half * 1024;
                int ixj = i ^ j;
                if (ixj > i) {
                    u64 a = hb.buf[i], b = hb.buf[ixj];
                    bool asc = ((i & ksz) == 0);
                    if (asc ? (a > b) : (a < b)) { hb.buf[i] = b; hb.buf[ixj] = a; }
                }
            }
            __syncthreads();
        }
    }
    for (int i = tid; i < kRem; i += 1024) {
        int p = atomicAdd(&g_cnt[6], 1);
        g_pool[p] = hb.buf[2047 - i];
    }
}

// ---------------------------------------------------------------------------
// Final: hierarchical select of top 2048 from pool (parallel digit search),
// full sort, decode, emit. hist/buf overlaid to stay under 48KB static smem.
__global__ void __launch_bounds__(1024) k_final(float* __restrict__ out, int out_size)
{
    __shared__ __align__(16) HistBuf hb;
    __shared__ u64 s[2048];
    __shared__ int s_scan[1024];
    __shared__ u64 s_pref;
    __shared__ int s_kk, s_binCnt, s_bufCnt, s_aboveCnt;
    int tid = threadIdx.x;
    int cnt = g_cnt[6];
    if (cnt > 12288) cnt = 12288;
    const int K = 2048;

    s[tid] = 0ull; s[tid + 1024] = 0ull;
    if (cnt <= K) {
        __syncthreads();
        for (int i = tid; i < cnt; i += 1024) s[i] = g_pool[i];
        __syncthreads();
    } else {
        if (tid == 0) { s_pref = 0ull; s_kk = K; s_aboveCnt = 0; s_bufCnt = 0; }
        int shift = 52;
        for (;;) {
            for (int i = tid; i < 4096; i += 1024) hb.hist[i] = 0;
            __syncthreads();
            u64 pref = s_pref;
            for (int i = tid; i < cnt; i += 1024) {
                u64 key = g_pool[i];
                bool m = (shift == 52) ? true : ((key >> (shift + 12)) == pref);
                if (m) atomicAdd(&hb.hist[(int)((key >> shift) & 4095)], 1);
            }
            __syncthreads();
            int kk_cur = s_kk;
            int jbase = tid * 4;
            int part = 0;
            #pragma unroll
            for (int qq = 0; qq < 4; ++qq) part += hb.hist[4095 - (jbase + qq)];
            s_scan[tid] = part;
            __syncthreads();
            for (int off = 1; off < 1024; off <<= 1) {
                int v = s_scan[tid];
                int add = (tid >= off) ? s_scan[tid - off] : 0;
                __syncthreads();
                s_scan[tid] = v + add;
                __syncthreads();
            }
            int incl = s_scan[tid];
            int base = incl - part;
            if (base < kk_cur && kk_cur <= incl) {
                int cum = base;
                #pragma unroll
                for (int qq = 0; qq < 4; ++qq) {
                    int d = 4095 - (jbase + qq);
                    int hh = hb.hist[d];
                    cum += hh;
                    if (cum >= kk_cur) {
                        s_kk = kk_cur - (cum - hh);
                        s_binCnt = hh;
                        s_pref = (s_pref << 12) | (u64)d;
                        break;
                    }
                }
            }
            __syncthreads();
            if (s_binCnt <= 2048 || shift == 4) break;
            shift -= 12;
        }
        int kRem = s_kk;
        u64 pref = s_pref;
        __syncthreads();
        hb.buf[tid] = 0ull; hb.buf[tid + 1024] = 0ull;
        __syncthreads();
        for (int i = tid; i < cnt; i += 1024) {
            u64 key = g_pool[i];
            u64 hi = key >> shift;
            if (hi > pref) {
                int p = atomicAdd(&s_aboveCnt, 1);
                s[p] = key;
            } else if (hi == pref) {
                int p = atomicAdd(&s_bufCnt, 1);
                if (p < 2048) hb.buf[p] = key;
            }
        }
        __syncthreads();
        for (int ksz = 2; ksz <= 2048; ksz <<= 1) {
            for (int j = ksz >> 1; j > 0; j >>= 1) {
                #pragma unroll
                for (int half = 0; half < 2; ++half) {
                    int i = tid + half * 1024;
                    int ixj = i ^ j;
                    if (ixj > i) {
                        u64 a = hb.buf[i], b = hb.buf[ixj];
                        bool asc = ((i & ksz) == 0);
                        if (asc ? (a > b) : (a < b)) { hb.buf[i] = b; hb.buf[ixj] = a; }
                    }
                }
                __syncthreads();
            }
        }
        int above = s_aboveCnt;   // == K - kRem
        for (int i = tid; i < kRem; i += 1024) s[above + i] = hb.buf[2047 - i];
        __syncthreads();
    }

    for (int ksz = 2; ksz <= 2048; ksz <<= 1) {
        for (int j = ksz >> 1; j > 0; j >>= 1) {
            #pragma unroll
            for (int half = 0; half < 2; ++half) {
                int i = tid + half * 1024;
                int ixj = i ^ j;
                if (ixj > i) {
                    u64 a = s[i], b = s[ixj];
                    bool asc = ((i & ksz) == 0);
                    if (asc ? (a > b) : (a < b)) { s[i] = b; s[ixj] = a; }
                }
            }
            __syncthreads();
        }
    }

    bool haveL = (out_size >= 12288);
    bool haveR = (out_size >= 14336) || (out_size < 12288);
    int rbase  = (out_size >= 14336) ? 12288 : 0;
    for (int r = tid; r < 2048; r += 1024) {
        u64 key = s[2047 - r];
        int pix = 0x7FFFFF - (int)(key & 0x7FFFFF);
        int lvl = 5 - (int)((key >> 23) & 7);
        float scv = __uint_as_float((unsigned)(key >> 26) & 0x7FFFFFFFu);
        int Wl = c_W[lvl];
        int py = pix / Wl, px = pix - py * Wl;
        float f  = c_fact[lvl], sg = c_scal[lvl];
        float fx = __fmul_rn((float)px, f);
        float fy = __fmul_rn((float)py, f);
        if (haveL) {
            float* L = out + (size_t)r * 6;
            L[0] = sg; L[1] = 0.f; L[2] = fx;
            L[3] = 0.f; L[4] = sg; L[5] = fy;
        }
        if (haveR) out[rbase + r] = scv;
    }
}

// ---------------------------------------------------------------------------
extern "C" void kernel_launch(void* const* d_in, const int* in_sizes, int n_in,
                              void* d_out, int out_size)
{
    const float* img = (const float*)d_in[0];
    const float* cw  = (const float*)d_in[1];
    const float* cb  = (const float*)d_in[2];
    float* out = (float*)d_out;

    void *p_up, *p_i2, *p_i3, *p_i4, *p_i5, *p_bB;
    cudaGetSymbolAddress(&p_up, g_imgup);
    cudaGetSymbolAddress(&p_i2, g_img2);
    cudaGetSymbolAddress(&p_i3, g_img3);
    cudaGetSymbolAddress(&p_i4, g_img4);
    cudaGetSymbolAddress(&p_i5, g_img5);
    cudaGetSymbolAddress(&p_bB, g_blurB);
    float *imgup=(float*)p_up, *img2=(float*)p_i2, *img3=(float*)p_i3,
          *img4=(float*)p_i4, *img5=(float*)p_i5, *bB=(float*)p_bB;

    // gaussian 5-tap, sigma=1 (identical host math to passing kernels)
    float gx[5] = {4.f, 1.f, 0.f, 1.f, 4.f};
    float g[5], gs = 0.f;
    for (int i = 0; i < 5; ++i) { g[i] = expf(-gx[i] * 0.5f); gs += g[i]; }
    for (int i = 0; i < 5; ++i) g[i] /= gs;

    k_init<<<26, 256>>>();                                                  // #1

    // level 0: upscale 2048 -> 2896
    k_resize2<<<dim3(3, 2896), 256>>>(img, 2048, imgup, 2896, 2896, 0);     // #2

    // pyramid levels 2-3 prerequisites
    k_blurVH<<<dim3(5, 256), 128>>>(img, bB, 2048, 2048, 2048, g[0], g[1], g[2]);   // #3
    k_resize2<<<dim3(2, 1448), 256>>>(bB, 2048, img2, 1448, 1448, 2896);            // #4
    k_blurVH<<<dim3(3, 181), 128>>>(img2, bB, 1448, 1448, 1448, g[0], g[1], g[2]);  // #5

    // detection for levels 0-1 (needs only img + imgup) -- captured by ncu -s 5
    k_convnms<<<3196, 160>>>(img, cw, cb, 0);                               // #6

    // rest of pyramid
    k_resize2<<<dim3(1, 1023), 256>>>(bB, 1448, img3, 1024, 1023, 4344);    // #7
    k_blurVH<<<dim3(3, 128), 128>>>(img3, bB, 1024, 1023, 1023, g[0], g[1], g[2]);  // #8
    k_resize2<<<dim3(1, 723), 256>>>(bB, 1024, img4, 724, 723, 5367);       // #9
    k_blurVH<<<dim3(2, 91), 128>>>(img4, bB, 724, 723, 723, g[0], g[1], g[2]);      // #10
    k_resize2<<<dim3(1, 511), 256>>>(bB, 724, img5, 512, 511, 6090);        // #11

    // detection for levels 2-5
    k_convnms<<<1045, 160>>>(img, cw, cb, 3196);                            // #12

    // column check (all levels, 32-row chunked)
    k_colcheck<<<1066, 128>>>();                                            // #13

    // selection
    k_select6<<<6, 1024>>>();                                               // #14
    k_final<<<1, 1024>>>(out, out_size);                                    // #15
}

// round 16
// speedup vs baseline: 1.1592x; 1.0446x over previous
#include <cuda_runtime.h>
#include <math.h>
#include <stdint.h>

typedef unsigned long long u64;

#define CAP 65536

// ---- device scratch (no allocations allowed) ----
__device__ float    g_imgup[2896*2896];
__device__ float    g_img2 [1448*1448];
__device__ float    g_img3 [1024*1023];
__device__ float    g_img4 [724*723];
__device__ float    g_img5 [512*511];
__device__ float    g_blurB[2048*2048];
__device__ float    g_rmax [16510464];
__device__ unsigned g_mask [518784];
__device__ float4   g_rtab [6601];
__device__ u64      g_cand[6*CAP];
__device__ u64      g_pool[12288];
__device__ int      g_cnt[8];   // [0..5]=per-level cand count, [6]=pool

__constant__ int   c_W[6]    = {2896,2048,1448,1023,723,511};
__constant__ int   c_S[6]    = {2896,2048,1448,1024,724,512};
__constant__ int   c_off[6]  = {0, 8386816, 12581120, 14677824, 15725376, 16248832};
__constant__ int   c_mS[6]   = {91,64,46,32,23,16};
__constant__ int   c_moff[6] = {0, 263536, 394608, 461216, 493952, 510581};
__constant__ float c_fact[6] = {(float)(2048.0/2896.0), 1.0f, (float)(2048.0/1448.0),
                                (float)(2048.0/1023.0), (float)(2048.0/723.0), (float)(2048.0/511.0)};
__constant__ float c_scal[6] = {(float)(2048.0/2896.0*22.0), 22.0f, (float)(2048.0/1448.0*22.0),
                                (float)(2048.0/1023.0*22.0), (float)(2048.0/723.0*22.0), (float)(2048.0/511.0*22.0)};
__constant__ int   c_k[6]    = {1040,1560,1820,1950,2015,2047};

// convnms tile tables: blocks/level = ceil(W/512) x ceil(W/8)
__constant__ int c_cumNC[6] = {0, 2172, 3196, 3739, 3995, 4177};   // total 4241
__constant__ int c_bx[6]    = {6, 4, 3, 2, 2, 1};
// colcheck (4-row blocks) tables: blocks/level = ceil(W/512) x ceil(W/4)
__constant__ int c_cumC4[6] = {0, 4344, 6392, 7478, 7990, 8352};   // total 8480

// resize-weight-table layout
__constant__ int   c_toff[5] = {0, 2896, 4344, 5367, 6090};        // total 6601
__constant__ int   c_rsw[5]  = {2048, 2048, 1448, 1023, 723};
__constant__ float c_rinv[5] = {(float)(2048.0/2896.0), (float)(2048.0/1448.0),
                                (float)(1448.0/1023.0), (float)(1023.0/723.0),
                                (float)(723.0/511.0)};

union HistBuf { int hist[4096]; u64 buf[2048]; };

__device__ __forceinline__ float4 f4max(float4 a, float4 b)
{
    return make_float4(fmaxf(a.x,b.x), fmaxf(a.y,b.y), fmaxf(a.z,b.z), fmaxf(a.w,b.w));
}

// ---------------------------------------------------------------------------
// init: zero counters + build resize weight tables (bit-identical arithmetic
// to the per-pixel resize math of the R5 passing kernel).
__global__ void __launch_bounds__(256) k_init()
{
    int idx = blockIdx.x * 256 + threadIdx.x;
    if (idx < 8) g_cnt[idx] = 0;
    if (idx >= 6601) return;
    int r = 4;
    while (idx < c_toff[r]) --r;
    int d  = idx - c_toff[r];
    int sw = c_rsw[r];
    float invs = c_rinv[r];

    float sx = __fadd_rn(__fmul_rn(__fadd_rn((float)d, 0.5f), invs), -0.5f);
    int j0 = (int)floorf(sx), j1 = j0 + 1;
    float w0 = __fadd_rn(1.0f, -__fadd_rn(sx, -(float)j0));
    float w1 = __fadd_rn(1.0f, -__fadd_rn((float)j1, -sx));
    bool v0 = (j0 >= 0), v1 = (j1 <= sw - 1);
    int C0 = v0 ? j0 : 0, C1 = v1 ? j1 : sw - 1;
    float n0, n1;
    if (v0 && v1) {
        float tot = __fadd_rn(w0, w1);
        n0 = __fdiv_rn(w0, tot); n1 = __fdiv_rn(w1, tot);
    } else if (v0) { n0 = 1.0f; n1 = 0.0f; }
    else           { n0 = 0.0f; n1 = 1.0f; }
    g_rtab[idx] = make_float4(n0, n1, __int_as_float(C0), __int_as_float(C1));
}

// ---------------------------------------------------------------------------
// Table-driven bilinear resize (jax half-pixel semantics baked into tables).
__global__ void __launch_bounds__(256) k_resize2(const float* __restrict__ in, int sIn,
                         float* __restrict__ dst, int sOut, int dw, int tab)
{
    int dy  = blockIdx.y;
    int dx0 = (blockIdx.x * 256 + threadIdx.x) * 4;
    if (dx0 >= dw) return;

    float4 ye = g_rtab[tab + dy];
    float n0y = ye.x, n1y = ye.y;
    const float* r0 = in + (size_t)__float_as_int(ye.z) * sIn;
    const float* r1 = in + (size_t)__float_as_int(ye.w) * sIn;

    float res[4];
    int nn = dw - dx0; if (nn > 4) nn = 4;
    #pragma unroll
    for (int c = 0; c < 4; ++c) {
        if (c >= nn) break;
        float4 xe = g_rtab[tab + dx0 + c];
        float n0x = xe.x, n1x = xe.y;
        int cx0 = __float_as_int(xe.z), cx1 = __float_as_int(xe.w);
        float p00 = __ldg(r0 + cx0), p01 = __ldg(r0 + cx1);
        float p10 = __ldg(r1 + cx0), p11 = __ldg(r1 + cx1);
        float c0 = __fadd_rn(__fmul_rn(n0y, p00), __fmul_rn(n1y, p10));
        float c1 = __fadd_rn(__fmul_rn(n0y, p01), __fmul_rn(n1y, p11));
        res[c] = __fadd_rn(__fmul_rn(n0x, c0), __fmul_rn(n1x, c1));
    }
    float* orow = dst + (size_t)dy * sOut;
    if (nn == 4) *(float4*)(orow + dx0) = make_float4(res[0], res[1], res[2], res[3]);
    else for (int c = 0; c < nn; ++c) orow[dx0 + c] = res[c];
}

// ---------------------------------------------------------------------------
__device__ __forceinline__ int reflect_i(int i, int n)
{
    if (i < 0) return -i;
    if (i >= n) return 2 * n - 2 - i;
    return i;
}

// Fused separable 5-tap gaussian blur (reflect): V in registers, H via smem.
__global__ void __launch_bounds__(128) k_blurVH(const float* __restrict__ in,
        float* __restrict__ out, int S, int W, int H,
        float g0, float g1, float g2)
{
    __shared__ __align__(16) float sv[8][512];
    int t  = threadIdx.x;
    int xb = blockIdx.x * 504;
    int yb = blockIdx.y * 8;
    int xg = xb - 4 + t * 4;

    float4 raw[12];
    bool fast = (xg >= 0) && (xg + 4 <= W);
    #pragma unroll
    for (int r = 0; r < 12; ++r) {
        const float* rowp = in + (size_t)reflect_i(yb - 2 + r, H) * S;
        if (fast) {
            raw[r] = __ldg((const float4*)(rowp + xg));
        } else {
            float t0 = __ldg(rowp + reflect_i(xg,     W));
            float t1 = __ldg(rowp + reflect_i(xg + 1, W));
            float t2 = __ldg(rowp + reflect_i(xg + 2, W));
            float t3 = __ldg(rowp + reflect_i(xg + 3, W));
            raw[r] = make_float4(t0, t1, t2, t3);
        }
    }
    #pragma unroll
    for (int r = 0; r < 8; ++r) {
        float4 a = raw[r], b = raw[r+1], c = raw[r+2], d = raw[r+3], e = raw[r+4];
        float4 vb;
        vb.x = fmaf(g0, e.x, fmaf(g1, d.x, fmaf(g2, c.x, fmaf(g1, b.x, g0 * a.x))));
        vb.y = fmaf(g0, e.y, fmaf(g1, d.y, fmaf(g2, c.y, fmaf(g1, b.y, g0 * a.y))));
        vb.z = fmaf(g0, e.z, fmaf(g1, d.z, fmaf(g2, c.z, fmaf(g1, b.z, g0 * a.z))));
        vb.w = fmaf(g0, e.w, fmaf(g1, d.w, fmaf(g2, c.w, fmaf(g1, b.w, g0 * a.w))));
        *(float4*)&sv[r][t * 4] = vb;
    }
    __syncthreads();
    if (t >= 126) return;
    int xo = xb + t * 4;
    if (xo >= W) return;
    #pragma unroll
    for (int r = 0; r < 8; ++r) {
        int yo = yb + r;
        if (yo >= H) break;
        float v[12];
        #pragma unroll
        for (int q = 0; q < 3; ++q) {
            float4 a = *(float4*)&sv[r][t * 4 + q * 4];
            v[q*4] = a.x; v[q*4+1] = a.y; v[q*4+2] = a.z; v[q*4+3] = a.w;
        }
        float res[4];
        #pragma unroll
        for (int c = 0; c < 4; ++c) {
            res[c] = fmaf(g0, v[c + 6], fmaf(g1, v[c + 5],
                     fmaf(g2, v[c + 4], fmaf(g1, v[c + 3], g0 * v[c + 2]))));
        }
        float* orow = out + (size_t)yo * S;
        if (xo + 4 <= W) {
            *(float4*)(orow + xo) = make_float4(res[0], res[1], res[2], res[3]);
        } else {
            for (int c = 0; c < 4; ++c) if (xo + c < W) orow[xo + c] = res[c];
        }
    }
}

// ---------------------------------------------------------------------------
// Merged (all levels) 8-row-tile fused conv + border-mask + row-max + semi-mask.
// Row-PAIR conv (ky asc, kx asc -- bit-identical FMA order); rolling 2-row sc.
__global__ void __launch_bounds__(160) k_convnms(const float* __restrict__ imgOrig,
        const float* __restrict__ wp, const float* __restrict__ bp)
{
    __shared__ float swt[25];
    __shared__ float sbv;
    __shared__ __align__(16) float raw[12][536];
    __shared__ __align__(16) float sc[2][528];
    __shared__ unsigned char nib[8][128];
    int t = threadIdx.x;
    if (t < 25) swt[t] = __ldg(wp + t);
    if (t == 31) sbv = __ldg(bp);

    int bid = blockIdx.x;
    int l = 5;
    while (bid < c_cumNC[l]) --l;
    int rem  = bid - c_cumNC[l];
    int bx   = c_bx[l];
    int yblk = rem / bx;
    int xblk = rem - yblk * bx;
    int W = c_W[l], H = W, S = c_S[l];
    const float* img;
    switch (l) {
        case 0: img = g_imgup; break;
        case 1: img = imgOrig; break;
        case 2: img = g_img2;  break;
        case 3: img = g_img3;  break;
        case 4: img = g_img4;  break;
        default: img = g_img5; break;
    }
    int y0 = yblk * 8, xb = xblk * 512;

    bool xfast = (xb >= 12) && (xb + 524 <= W);
    #pragma unroll
    for (int r = 0; r < 12; ++r) {
        int yy = y0 - 2 + r;
        yy = yy < 0 ? 0 : (yy > H - 1 ? H - 1 : yy);
        const float* rp = img + (size_t)yy * S;
        if (xfast) {
            if (t < 134)
                *(float4*)&raw[r][t * 4] = __ldg((const float4*)(rp + xb - 12 + t * 4));
        } else {
            for (int i = t; i < 536; i += 160) {
                int x = xb - 12 + i;
                x = x < 0 ? 0 : (x > W - 1 ? W - 1 : x);
                raw[r][i] = __ldg(rp + x);
            }
        }
    }
    __syncthreads();

    float wreg[25];
    float breg = 0.f;
    if (t < 132) {
        #pragma unroll
        for (int i = 0; i < 25; ++i) wreg[i] = swt[i];
        breg = sbv;
    }
    int tc = t * 4;
    float* rbase = g_rmax + c_off[l];

    #pragma unroll
    for (int pr = 0; pr < 4; ++pr) {
        int rA = pr * 2;
        if (t < 132) {
            float a0[4], a1[4];
            #pragma unroll
            for (int c = 0; c < 4; ++c) { a0[c] = breg; a1[c] = breg; }
            #pragma unroll
            for (int z = 0; z < 6; ++z) {
                float4 A = *(const float4*)&raw[rA + z][tc];
                float4 B = *(const float4*)&raw[rA + z][tc + 4];
                float4 C = *(const float4*)&raw[rA + z][tc + 8];
                float v[12] = {A.x,A.y,A.z,A.w, B.x,B.y,B.z,B.w, C.x,C.y,C.z,C.w};
                if (z <= 4) {
                    const float* wr = &wreg[z * 5];
                    #pragma unroll
                    for (int c = 0; c < 4; ++c) {
                        a0[c] = fmaf(wr[0], v[2 + c], a0[c]);
                        a0[c] = fmaf(wr[1], v[3 + c], a0[c]);
                        a0[c] = fmaf(wr[2], v[4 + c], a0[c]);
                        a0[c] = fmaf(wr[3], v[5 + c], a0[c]);
                        a0[c] = fmaf(wr[4], v[6 + c], a0[c]);
                    }
                }
                if (z >= 1) {
                    const float* wr = &wreg[(z - 1) * 5];
                    #pragma unroll
                    for (int c = 0; c < 4; ++c) {
                        a1[c] = fmaf(wr[0], v[2 + c], a1[c]);
                        a1[c] = fmaf(wr[1], v[3 + c], a1[c]);
                        a1[c] = fmaf(wr[2], v[4 + c], a1[c]);
                        a1[c] = fmaf(wr[3], v[5 + c], a1[c]);
                        a1[c] = fmaf(wr[4], v[6 + c], a1[c]);
                    }
                }
            }
            int xg = xb - 8 + tc;
            #pragma unroll
            for (int h = 0; h < 2; ++h) {
                int yv = y0 + rA + h;
                bool rowok = (yv >= 15 && yv < H - 15);
                float* ap = h ? a1 : a0;
                float4 o;
                o.x = (rowok && xg + 0 >= 15 && xg + 0 < W - 15) ? ap[0] : 0.f;
                o.y = (rowok && xg + 1 >= 15 && xg + 1 < W - 15) ? ap[1] : 0.f;
                o.z = (rowok && xg + 2 >= 15 && xg + 2 < W - 15) ? ap[2] : 0.f;
                o.w = (rowok && xg + 3 >= 15 && xg + 3 < W - 15) ? ap[3] : 0.f;
                *(float4*)&sc[h][tc] = o;
            }
        }
        __syncthreads();

        if (t < 128) {
            #pragma unroll
            for (int h = 0; h < 2; ++h) {
                int r = rA + h;
                float4 q0 = *(const float4*)&sc[h][tc];
                float4 q1 = *(const float4*)&sc[h][tc + 4];
                float4 q2 = *(const float4*)&sc[h][tc + 8];
                float4 q3 = *(const float4*)&sc[h][tc + 12];
                float4 q4 = *(const float4*)&sc[h][tc + 16];
                float f[20] = {q0.x,q0.y,q0.z,q0.w, q1.x,q1.y,q1.z,q1.w,
                               q2.x,q2.y,q2.z,q2.w, q3.x,q3.y,q3.z,q3.w,
                               q4.x,q4.y,q4.z,q4.w};
                float run = f[15];
                #pragma unroll
                for (int i = 14; i >= 5; --i) run = fmaxf(run, f[i]);
                float suf4 = fmaxf(run, f[4]);
                float suf3 = fmaxf(suf4, f[3]);
                float suf2 = fmaxf(suf3, f[2]);
                float suf1 = fmaxf(suf2, f[1]);
                float r0 = suf1;
                float run2 = f[16];
                float r1 = fmaxf(suf2, run2);
                run2 = fmaxf(run2, f[17]);
                float r2 = fmaxf(suf3, run2);
                run2 = fmaxf(run2, f[18]);
                float r3 = fmaxf(suf4, run2);
                float s0 = f[8], s1 = f[9], s2 = f[10], s3 = f[11];
                unsigned nb = 0;
                if (s0 > 0.f && s0 == r0) nb |= 1u;
                if (s1 > 0.f && s1 == r1) nb |= 2u;
                if (s2 > 0.f && s2 == r2) nb |= 4u;
                if (s3 > 0.f && s3 == r3) nb |= 8u;
                nib[r][t] = (unsigned char)nb;
                int yv = y0 + r;
                int x0 = xb + tc;
                if (yv < H && x0 < S)
                    *(float4*)(rbase + (size_t)yv * S + x0) = make_float4(r0, r1, r2, r3);
            }
        }
        __syncthreads();
    }

    if (t < 128) {
        int r = t >> 4, w = t & 15;
        unsigned word = 0;
        #pragma unroll
        for (int q = 0; q < 8; ++q)
            word |= ((unsigned)nib[r][w * 8 + q]) << (q * 4);
        int yv = y0 + r;
        int wi = xblk * 16 + w;
        if (yv < H && wi < c_mS[l])
            g_mask[c_moff[l] + yv * c_mS[l] + wi] = word;
    }
}

// ---------------------------------------------------------------------------
// Column-max check, 4-row blocks (max latency hiding). core = max(v[3..14])
// shared across the 4 windows; fmaxf is exact so results are bit-identical.
__global__ void __launch_bounds__(128) k_colcheck()
{
    int bid = blockIdx.x;
    int l = 5;
    while (bid < c_cumC4[l]) --l;
    int rem  = bid - c_cumC4[l];
    int bx   = c_bx[l];
    int yblk = rem / bx;
    int xblk = rem - yblk * bx;
    int W = c_W[l], H = W, S = c_S[l];
    const float* rmax = g_rmax + c_off[l];
    const unsigned* mrow = g_mask + c_moff[l];
    int mS = c_mS[l];

    int x4 = xblk * 512 + threadIdx.x * 4;
    if (x4 >= W) return;
    int y0 = yblk * 4;

    unsigned nb[4]; unsigned any = 0;
    #pragma unroll
    for (int o = 0; o < 4; ++o) {
        int y = y0 + o;
        unsigned m = (y < H) ? __ldg(mrow + y * mS + (x4 >> 5)) : 0u;
        nb[o] = (m >> (x4 & 31)) & 15u;
        any |= nb[o];
    }
    if (!any) return;

    float4 v[18];
    #pragma unroll
    for (int j = 0; j < 18; ++j) {
        int yy = y0 - 7 + j;
        yy = yy < 0 ? 0 : (yy > H - 1 ? H - 1 : yy);
        v[j] = __ldg((const float4*)(rmax + (size_t)yy * S + x4));
    }
    float4 core = v[3];
    #pragma unroll
    for (int j = 4; j <= 14; ++j) core = f4max(core, v[j]);
    float4 m[4];
    m[0] = f4max(f4max(f4max(core, v[0]), v[1]), v[2]);
    m[1] = f4max(f4max(f4max(core, v[1]), v[2]), v[15]);
    m[2] = f4max(f4max(f4max(core, v[2]), v[15]), v[16]);
    m[3] = f4max(f4max(f4max(core, v[15]), v[16]), v[17]);

    #pragma unroll
    for (int o = 0; o < 4; ++o) {
        int y = y0 + o;
        if (y >= H) break;
        if (!nb[o]) continue;
        float4 ctr = v[o + 7];
        const float* sp = (const float*)&ctr;
        const float* mp = (const float*)&m[o];
        #pragma unroll
        for (int cc = 0; cc < 4; ++cc) {
            if (!((nb[o] >> cc) & 1u)) continue;
            int x = x4 + cc;
            float s = sp[cc];
            if (x < W && s == mp[cc]) {
                unsigned sbits = __float_as_uint(s) | 0x80000000u;
                int pix = y * W + x;
                u64 key = ((u64)sbits << 26) | ((u64)(5 - l) << 23)
                        | (u64)(0x7FFFFF - pix);
                int pos = atomicAdd(&g_cnt[l], 1);
                if (pos < CAP) g_cand[(size_t)l * CAP + pos] = key;
            }
        }
    }
}

// ---------------------------------------------------------------------------
// Hierarchical per-level select (block l -> level l): 12-bit histogram levels
// with PARALLEL suffix-scan digit search, one classify pass, exact boundary-bin
// bitonic sort. hist/buf overlaid.
__global__ void __launch_bounds__(1024) k_select6()
{
    __shared__ __align__(16) HistBuf hb;
    __shared__ int s_scan[1024];
    __shared__ u64 s_pref;
    __shared__ int s_kk, s_binCnt, s_bufCnt;
    int l   = blockIdx.x;
    int tid = threadIdx.x;
    const u64* src = g_cand + (size_t)l * CAP;
    int k   = c_k[l];
    int cnt = g_cnt[l];
    if (cnt > CAP) cnt = CAP;

    if (cnt <= k) {
        for (int i = tid; i < cnt; i += 1024) {
            int p = atomicAdd(&g_cnt[6], 1);
            g_pool[p] = src[i];
        }
        return;
    }

    if (tid == 0) { s_pref = 0ull; s_kk = k; }
    int shift = 52;
    for (;;) {
        for (int i = tid; i < 4096; i += 1024) hb.hist[i] = 0;
        __syncthreads();
        u64 pref = s_pref;
        for (int i = tid; i < cnt; i += 1024) {
            u64 key = src[i];
            bool m = (shift == 52) ? true : ((key >> (shift + 12)) == pref);
            if (m) atomicAdd(&hb.hist[(int)((key >> shift) & 4095)], 1);
        }
        __syncthreads();
        int kk_cur = s_kk;
        int jbase = tid * 4;
        int part = 0;
        #pragma unroll
        for (int qq = 0; qq < 4; ++qq) part += hb.hist[4095 - (jbase + qq)];
        s_scan[tid] = part;
        __syncthreads();
        for (int off = 1; off < 1024; off <<= 1) {
            int v = s_scan[tid];
            int add = (tid >= off) ? s_scan[tid - off] : 0;
            __syncthreads();
            s_scan[tid] = v + add;
            __syncthreads();
        }
        int incl = s_scan[tid];
        int base = incl - part;
        if (base < kk_cur && kk_cur <= incl) {
            int cum = base;
            #pragma unroll
            for (int qq = 0; qq < 4; ++qq) {
                int d = 4095 - (jbase + qq);
                int hh = hb.hist[d];
                cum += hh;
                if (cum >= kk_cur) {
                    s_kk = kk_cur - (cum - hh);
                    s_binCnt = hh;
                    s_pref = (s_pref << 12) | (u64)d;
                    break;
                }
            }
        }
        __syncthreads();
        if (s_binCnt <= 2048 || shift == 4) break;
        shift -= 12;
    }
    int kRem = s_kk;
    u64 pref = s_pref;
    if (tid == 0) s_bufCnt = 0;
    __syncthreads();
    hb.buf[tid] = 0ull; hb.buf[tid + 1024] = 0ull;
    __syncthreads();

    for (int i = tid; i < cnt; i += 1024) {
        u64 key = src[i];
        u64 hi = key >> shift;
        if (hi > pref) {
            int p = atomicAdd(&g_cnt[6], 1);
            g_pool[p] = key;
        } else if (hi == pref) {
            int p = atomicAdd(&s_bufCnt, 1);
            if (p < 2048) hb.buf[p] = key;
        }
    }
    __syncthreads();

    for (int ksz = 2; ksz <= 2048; ksz <<= 1) {
        for (int j = ksz >> 1; j > 0; j >>= 1) {
            #pragma unroll
            for (int half = 0; half < 2; ++half) {
                int i = tid + half * 1024;
                int ixj = i ^ j;
                if (ixj > i) {
                    u64 a = hb.buf[i], b = hb.buf[ixj];
                    bool asc = ((i & ksz) == 0);
                    if (asc ? (a > b) : (a < b)) { hb.buf[i] = b; hb.buf[ixj] = a; }
                }
            }
            __syncthreads();
        }
    }
    for (int i = tid; i < kRem; i += 1024) {
        int p = atomicAdd(&g_cnt[6], 1);
        g_pool[p] = hb.buf[2047 - i];
    }
}

// ---------------------------------------------------------------------------
// Final: hierarchical select of top 2048 from pool (parallel digit search),
// full sort, decode, emit. hist/buf overlaid to stay under 48KB static smem.
__global__ void __launch_bounds__(1024) k_final(float* __restrict__ out, int out_size)
{
    __shared__ __align__(16) HistBuf hb;
    __shared__ u64 s[2048];
    __shared__ int s_scan[1024];
    __shared__ u64 s_pref;
    __shared__ int s_kk, s_binCnt, s_bufCnt, s_aboveCnt;
    int tid = threadIdx.x;
    int cnt = g_cnt[6];
    if (cnt > 12288) cnt = 12288;
    const int K = 2048;

    s[tid] = 0ull; s[tid + 1024] = 0ull;
    if (cnt <= K) {
        __syncthreads();
        for (int i = tid; i < cnt; i += 1024) s[i] = g_pool[i];
        __syncthreads();
    } else {
        if (tid == 0) { s_pref = 0ull; s_kk = K; s_aboveCnt = 0; s_bufCnt = 0; }
        int shift = 52;
        for (;;) {
            for (int i = tid; i < 4096; i += 1024) hb.hist[i] = 0;
            __syncthreads();
            u64 pref = s_pref;
            for (int i = tid; i < cnt; i += 1024) {
                u64 key = g_pool[i];
                bool m = (shift == 52) ? true : ((key >> (shift + 12)) == pref);
                if (m) atomicAdd(&hb.hist[(int)((key >> shift) & 4095)], 1);
            }
            __syncthreads();
            int kk_cur = s_kk;
            int jbase = tid * 4;
            int part = 0;
            #pragma unroll
            for (int qq = 0; qq < 4; ++qq) part += hb.hist[4095 - (jbase + qq)];
            s_scan[tid] = part;
            __syncthreads();
            for (int off = 1; off < 1024; off <<= 1) {
                int v = s_scan[tid];
                int add = (tid >= off) ? s_scan[tid - off] : 0;
                __syncthreads();
                s_scan[tid] = v + add;
                __syncthreads();
            }
            int incl = s_scan[tid];
            int base = incl - part;
            if (base < kk_cur && kk_cur <= incl) {
                int cum = base;
                #pragma unroll
                for (int qq = 0; qq < 4; ++qq) {
                    int d = 4095 - (jbase + qq);
                    int hh = hb.hist[d];
                    cum += hh;
                    if (cum >= kk_cur) {
                        s_kk = kk_cur - (cum - hh);
                        s_binCnt = hh;
                        s_pref = (s_pref << 12) | (u64)d;
                        break;
                    }
                }
            }
            __syncthreads();
            if (s_binCnt <= 2048 || shift == 4) break;
            shift -= 12;
        }
        int kRem = s_kk;
        u64 pref = s_pref;
        __syncthreads();
        hb.buf[tid] = 0ull; hb.buf[tid + 1024] = 0ull;
        __syncthreads();
        for (int i = tid; i < cnt; i += 1024) {
            u64 key = g_pool[i];
            u64 hi = key >> shift;
            if (hi > pref) {
                int p = atomicAdd(&s_aboveCnt, 1);
                s[p] = key;
            } else if (hi == pref) {
                int p = atomicAdd(&s_bufCnt, 1);
                if (p < 2048) hb.buf[p] = key;
            }
        }
        __syncthreads();
        for (int ksz = 2; ksz <= 2048; ksz <<= 1) {
            for (int j = ksz >> 1; j > 0; j >>= 1) {
                #pragma unroll
                for (int half = 0; half < 2; ++half) {
                    int i = tid + half * 1024;
                    int ixj = i ^ j;
                    if (ixj > i) {
                        u64 a = hb.buf[i], b = hb.buf[ixj];
                        bool asc = ((i & ksz) == 0);
                        if (asc ? (a > b) : (a < b)) { hb.buf[i] = b; hb.buf[ixj] = a; }
                    }
                }
                __syncthreads();
            }
        }
        int above = s_aboveCnt;   // == K - kRem
        for (int i = tid; i < kRem; i += 1024) s[above + i] = hb.buf[2047 - i];
        __syncthreads();
    }

    for (int ksz = 2; ksz <= 2048; ksz <<= 1) {
        for (int j = ksz >> 1; j > 0; j >>= 1) {
            #pragma unroll
            for (int half = 0; half < 2; ++half) {
                int i = tid + half * 1024;
                int ixj = i ^ j;
                if (ixj > i) {
                    u64 a = s[i], b = s[ixj];
                    bool asc = ((i & ksz) == 0);
                    if (asc ? (a > b) : (a < b)) { s[i] = b; s[ixj] = a; }
                }
            }
            __syncthreads();
        }
    }

    bool haveL = (out_size >= 12288);
    bool haveR = (out_size >= 14336) || (out_size < 12288);
    int rbase  = (out_size >= 14336) ? 12288 : 0;
    for (int r = tid; r < 2048; r += 1024) {
        u64 key = s[2047 - r];
        int pix = 0x7FFFFF - (int)(key & 0x7FFFFF);
        int lvl = 5 - (int)((key >> 23) & 7);
        float scv = __uint_as_float((unsigned)(key >> 26) & 0x7FFFFFFFu);
        int Wl = c_W[lvl];
        int py = pix / Wl, px = pix - py * Wl;
        float f  = c_fact[lvl], sg = c_scal[lvl];
        float fx = __fmul_rn((float)px, f);
        float fy = __fmul_rn((float)py, f);
        if (haveL) {
            float* L = out + (size_t)r * 6;
            L[0] = sg; L[1] = 0.f; L[2] = fx;
            L[3] = 0.f; L[4] = sg; L[5] = fy;
        }
        if (haveR) out[rbase + r] = scv;
    }
}

// ---------------------------------------------------------------------------
extern "C" void kernel_launch(void* const* d_in, const int* in_sizes, int n_in,
                              void* d_out, int out_size)
{
    const float* img = (const float*)d_in[0];
    const float* cw  = (const float*)d_in[1];
    const float* cb  = (const float*)d_in[2];
    float* out = (float*)d_out;

    void *p_up, *p_i2, *p_i3, *p_i4, *p_i5, *p_bB;
    cudaGetSymbolAddress(&p_up, g_imgup);
    cudaGetSymbolAddress(&p_i2, g_img2);
    cudaGetSymbolAddress(&p_i3, g_img3);
    cudaGetSymbolAddress(&p_i4, g_img4);
    cudaGetSymbolAddress(&p_i5, g_img5);
    cudaGetSymbolAddress(&p_bB, g_blurB);
    float *imgup=(float*)p_up, *img2=(float*)p_i2, *img3=(float*)p_i3,
          *img4=(float*)p_i4, *img5=(float*)p_i5, *bB=(float*)p_bB;

    // gaussian 5-tap, sigma=1 (identical host math to passing kernels)
    float gx[5] = {4.f, 1.f, 0.f, 1.f, 4.f};
    float g[5], gs = 0.f;
    for (int i = 0; i < 5; ++i) { g[i] = expf(-gx[i] * 0.5f); gs += g[i]; }
    for (int i = 0; i < 5; ++i) g[i] /= gs;

    k_init<<<26, 256>>>();

    // level 0: upscale 2048 -> 2896
    k_resize2<<<dim3(3, 2896), 256>>>(img, 2048, imgup, 2896, 2896, 0);

    // pyrdown chain: blur (fused V+H) then table-driven resize
    k_blurVH<<<dim3(5, 256), 128>>>(img, bB, 2048, 2048, 2048, g[0], g[1], g[2]);
    k_resize2<<<dim3(2, 1448), 256>>>(bB, 2048, img2, 1448, 1448, 2896);

    k_blurVH<<<dim3(3, 181), 128>>>(img2, bB, 1448, 1448, 1448, g[0], g[1], g[2]);
    k_resize2<<<dim3(1, 1023), 256>>>(bB, 1448, img3, 1024, 1023, 4344);

    k_blurVH<<<dim3(3, 128), 128>>>(img3, bB, 1024, 1023, 1023, g[0], g[1], g[2]);
    k_resize2<<<dim3(1, 723), 256>>>(bB, 1024, img4, 724, 723, 5367);

    k_blurVH<<<dim3(2, 91), 128>>>(img4, bB, 724, 723, 723, g[0], g[1], g[2]);
    k_resize2<<<dim3(1, 511), 256>>>(bB, 724, img5, 512, 511, 6090);

    // merged detection across all 6 levels
    k_convnms <<<4241, 160>>>(img, cw, cb);
    k_colcheck<<<8480, 128>>>();

    // selection
    k_select6<<<6, 1024>>>();
    k_final<<<1, 1024>>>(out, out_size);
}